// round 13
// baseline (speedup 1.0000x reference)
#include <cuda_runtime.h>
#include <math.h>

#define DIM 192
#define NB 12
#define BLKV 4096
#define THREADS 256
#define FULLM 0xffffffffu
#define NEG_INF (-3.402823466e+38f)

// accumulators: [0]=sum(p*g) [1]=sum(p*p) [2]=sum(g*g) [3]=loss_cl
__device__ double g_acc[4] = {0.0, 0.0, 0.0, 0.0};
__device__ unsigned g_count = 0;

__device__ __forceinline__ float warp_sum(float v) {
#pragma unroll
    for (int o = 16; o; o >>= 1) v += __shfl_xor_sync(FULLM, v, o);
    return v;
}

// ---------------------------------------------------------------------------
// Thread (x,y) owns the 16-voxel z-column. lane = (x&1)*16 + y:
//   y+-1 : lane+-1 shfl     x^1 : lane^16 shfl (always a valid x neighbor)
//   other x : published smem column, 1 guarded LDS
// gt is binary: its whole column is a 16-bit mask (bitwise erode=AND cross,
// dilate=OR box, delta = e & ~d, skel |= delta) -- exact vs f32 reference.
// Per erosion level ONE publish (f32 e_k 16 STS + bits b_k 1 STS) + ONE sync;
// both the dilate of level k and the erode to level k+1 read that publish.
// Buffers alternate 0/1; WAR safety comes from one-phase barrier distance.
// ---------------------------------------------------------------------------

// f32 erode: min over z+-1 (regs), x (shfl + smem), y (shfl); +inf pad
__device__ __forceinline__ void erode_f32(const float (&v)[16], float (&e)[16],
                                          const float* __restrict__ fb,
                                          int to, bool xv, int y) {
#pragma unroll
    for (int k = 0; k < 16; k++) {
        float m = v[k];
        if (k > 0)   m = fminf(m, v[k - 1]);
        if (k < 15)  m = fminf(m, v[k + 1]);
        m = fminf(m, __shfl_xor_sync(FULLM, v[k], 16));
        float o = fb[(k << 8) + to];
        if (xv) m = fminf(m, o);
        float yu = __shfl_up_sync(FULLM, v[k], 1);
        if (y > 0)  m = fminf(m, yu);
        float yd = __shfl_down_sync(FULLM, v[k], 1);
        if (y < 15) m = fminf(m, yd);
        e[k] = m;
    }
}

// f32 dilate (3x3x3 max, -inf pad) fused with skel init/update.
template <bool FIRST>
__device__ __forceinline__ void dilate_upd_f32(const float (&e)[16], const float (&prev)[16],
                                               float (&skel)[16],
                                               const float* __restrict__ fb,
                                               int to, bool xv, int y) {
    float xo0 = fb[to];
    float xo_m1 = NEG_INF;
#pragma unroll
    for (int k = 0; k < 16; k++) {
        float xo_p1 = (k < 15) ? fb[((k + 1) << 8) + to] : NEG_INF;
        // own z-max
        float mzk = e[k];
        if (k > 0)   mzk = fmaxf(mzk, e[k - 1]);
        if (k < 15)  mzk = fmaxf(mzk, e[k + 1]);
        // partner column z-max via one shfl of own z-max
        float m = fmaxf(mzk, __shfl_xor_sync(FULLM, mzk, 16));
        // other-x column z-max via rolling LDS window
        float zo = fmaxf(xo0, fmaxf(xo_m1, xo_p1));
        if (xv) m = fmaxf(m, zo);
        // y-pass on completed xz-max
        float yu = __shfl_up_sync(FULLM, m, 1);
        float yd = __shfl_down_sync(FULLM, m, 1);
        float d = m;
        if (y > 0)  d = fmaxf(d, yu);
        if (y < 15) d = fmaxf(d, yd);
        float delta = fmaxf(prev[k] - d, 0.0f);
        if (FIRST) {
            skel[k] = delta;
        } else {
            float s = skel[k];
            skel[k] = s + fmaxf(delta - s * delta, 0.0f);
        }
        xo_m1 = xo0; xo0 = xo_p1;
    }
}

// bits erode (AND 7-cross, pads=1) reading published bits
__device__ __forceinline__ unsigned erode_bits(unsigned cur, const unsigned* __restrict__ ib,
                                               int to, bool xv, int y) {
    unsigned m = cur & ((cur << 1) | 1u) & ((cur >> 1) | 0x8000u);
    m &= __shfl_xor_sync(FULLM, cur, 16);
    unsigned ox = ib[to];
    if (xv) m &= ox;
    unsigned yu = __shfl_up_sync(FULLM, cur, 1);
    if (y > 0)  m &= yu;
    unsigned yd = __shfl_down_sync(FULLM, cur, 1);
    if (y < 15) m &= yd;
    return m & 0xFFFFu;
}

// bits dilate (OR 3x3x3 box, pads=0); other-x dz recomputed from published e-bits
__device__ __forceinline__ unsigned dilate_bits(unsigned e, const unsigned* __restrict__ ib,
                                                int to, bool xv, int y) {
    unsigned dz = e | (e << 1) | (e >> 1);
    unsigned dx = dz | __shfl_xor_sync(FULLM, dz, 16);
    unsigned ox = ib[to];
    if (xv) dx |= ox | (ox << 1) | (ox >> 1);
    unsigned d = dx;
    unsigned yu = __shfl_up_sync(FULLM, dx, 1);
    if (y > 0)  d |= yu;
    unsigned yd = __shfl_down_sync(FULLM, dx, 1);
    if (y < 15) d |= yd;
    return d & 0xFFFFu;
}

__device__ __forceinline__ double block_tversky(double tp, double fn, double fp) {
    const double s = 1e-8;
    double ab = fp + fn + s;
    double alpha = 0.5 + 0.5 * (fp + s) / ab;
    double beta  = 0.5 + 0.5 * (fn + s) / ab;
    return 1.0 - (tp + s) / (tp + alpha * fp + beta * fn + s);
}

extern __shared__ float smem[];

__global__ void __launch_bounds__(THREADS, 3)
loss_main_kernel(const float* __restrict__ pred, const float* __restrict__ gt,
                 const float* __restrict__ w1, const float* __restrict__ w2,
                 float* __restrict__ out, int nblk) {
    float* fb0 = smem;                                  // f32 exchange, even phases
    float* fb1 = smem + BLKV;                           // f32 exchange, odd phases
    unsigned* ib0 = (unsigned*)(smem + 2 * BLKV);       // bits exchange, even
    unsigned* ib1 = ib0 + 256;                          // bits exchange, odd
    __shared__ float red[8][6];
    __shared__ unsigned last_flag;

    int t = threadIdx.x;
    int b = blockIdx.x;
    int by = b % NB;
    int bx = (b / NB) % NB;
    int bz = (b / (NB * NB)) % NB;
    int n  = b / (NB * NB * NB);

    long base = (long)n * DIM * DIM * DIM
              + (long)(bz * 16) * DIM * DIM
              + (long)(bx * 16) * DIM
              + (long)(by * 16);

    int x = t >> 4;
    int y = t & 15;
    bool xv = (x & 1) ? (x < 15) : (x > 0);
    int to = xv ? ((x & 1) ? t + 16 : t - 16) : t;
    int lane = t & 31, w = t >> 5;

    // ---- load: pred->f32 col, gt->bitmask; dice partials banked early ----
    float p[16];
    unsigned b0m = 0;
    {
        float pg = 0.f, pp = 0.f;
#pragma unroll
        for (int k = 0; k < 16; k++) {
            long gi = base + (long)k * DIM * DIM + x * DIM + y;
            float gv = gt[gi];
            float pv = pred[gi];
            p[k] = pv;
            if (gv != 0.0f) { b0m |= (1u << k); pg += pv; }
            pp += pv * pv;
        }
        float gg = (float)__popc(b0m);
        float s0 = warp_sum(pg), s1 = warp_sum(pp), s2 = warp_sum(gg);
        if (lane == 0) { red[w][0] = s0; red[w][1] = s1; red[w][2] = s2; }
    }

    // NOTE: reference's boundary conv kernel is -(ones.at[13].set(26)) -- all
    // taps negative -- so (b > 0.1) is identically false, loss_bdr == 0. Dropped.

    // ---- merged skeleton pipeline: 5 publish+sync phases ----
    float e1[16], skel[16];
    unsigned bA = b0m, bB, bskel = 0;

    // P0: publish e0=p/b0; erode -> e1/bB
#pragma unroll
    for (int k = 0; k < 16; k++) fb0[(k << 8) + t] = p[k];
    ib0[t] = bA;
    __syncthreads();
    erode_f32(p, e1, fb0, to, xv, y);
    bB = erode_bits(bA, ib0, to, xv, y);

    // P1: publish e1/bB; skel init with prev=p/bA; erode -> p=e2 / bA=b2
#pragma unroll
    for (int k = 0; k < 16; k++) fb1[(k << 8) + t] = e1[k];
    ib1[t] = bB;
    __syncthreads();
    dilate_upd_f32<true>(e1, p, skel, fb1, to, xv, y);
    bskel |= bA & ~dilate_bits(bB, ib1, to, xv, y);
    erode_f32(e1, p, fb1, to, xv, y);
    bA = erode_bits(bB, ib1, to, xv, y);

    // P2: publish e2(p)/b2(bA); update prev=e1/bB; erode -> e1=e3 / bB=b3
#pragma unroll
    for (int k = 0; k < 16; k++) fb0[(k << 8) + t] = p[k];
    ib0[t] = bA;
    __syncthreads();
    dilate_upd_f32<false>(p, e1, skel, fb0, to, xv, y);
    bskel |= bB & ~dilate_bits(bA, ib0, to, xv, y);
    erode_f32(p, e1, fb0, to, xv, y);
    bB = erode_bits(bA, ib0, to, xv, y);

    // P3: publish e3(e1)/b3(bB); update prev=p/bA; erode -> p=e4 / bA=b4
#pragma unroll
    for (int k = 0; k < 16; k++) fb1[(k << 8) + t] = e1[k];
    ib1[t] = bB;
    __syncthreads();
    dilate_upd_f32<false>(e1, p, skel, fb1, to, xv, y);
    bskel |= bA & ~dilate_bits(bB, ib1, to, xv, y);
    erode_f32(e1, p, fb1, to, xv, y);
    bA = erode_bits(bB, ib1, to, xv, y);

    // P4: publish e4(p)/b4(bA); final update prev=e1/bB (no erode)
#pragma unroll
    for (int k = 0; k < 16; k++) fb0[(k << 8) + t] = p[k];
    ib0[t] = bA;
    __syncthreads();
    dilate_upd_f32<false>(p, e1, skel, fb0, to, xv, y);
    bskel |= bB & ~dilate_bits(bA, ib0, to, xv, y);

    // ---- clDice tversky counts ----
    float tpc = 0.f, fnc = 0.f, fpc = 0.f;
#pragma unroll
    for (int k = 0; k < 16; k++) {
        float sp = skel[k];
        if ((bskel >> k) & 1u) {
            tpc += sp;
            fnc += 1.0f - sp;
        } else {
            fpc += sp;
        }
    }
    {
        float s3 = warp_sum(tpc), s4 = warp_sum(fnc), s5 = warp_sum(fpc);
        if (lane == 0) { red[w][3] = s3; red[w][4] = s4; red[w][5] = s5; }
    }
    __syncthreads();

    // ---- per-block accumulate + last-CTA finalize ----
    if (t == 0) {
        double s[6];
#pragma unroll
        for (int i = 0; i < 6; i++) {
            double acc = 0.0;
#pragma unroll
            for (int ww = 0; ww < 8; ww++) acc += (double)red[ww][i];
            s[i] = acc;
        }
        atomicAdd(&g_acc[0], s[0]);
        atomicAdd(&g_acc[1], s[1]);
        atomicAdd(&g_acc[2], s[2]);
        atomicAdd(&g_acc[3], block_tversky(s[3], s[4], s[5]));
        __threadfence();
        unsigned c = atomicAdd(&g_count, 1u);
        last_flag = (c == (unsigned)(nblk - 1)) ? 1u : 0u;
    }
    __syncthreads();

    if (last_flag && t == 0) {
        __threadfence();
        double pg = g_acc[0], pp = g_acc[1], gg = g_acc[2], cl = g_acc[3];
        double dice = 2.0 * pg / fmax(pp + gg, 1e-6);
        double dice_loss = 1.0 - dice;
        double w1s = (double)w1[0], w2s = (double)w2[0];
        double edge = (cl / (w2s * w2s)) / (2.0 * (double)nblk)
                    + log(1.0 + fabs(w1s) * fabs(w2s));
        out[0] = (float)((dice < 0.8) ? dice_loss : dice_loss + edge);
        // reset for the next (graph-replayed) call
        g_acc[0] = 0.0; g_acc[1] = 0.0; g_acc[2] = 0.0; g_acc[3] = 0.0;
        g_count = 0u;
        __threadfence();
    }
}

extern "C" void kernel_launch(void* const* d_in, const int* in_sizes, int n_in,
                              void* d_out, int out_size) {
    const float* pred = (const float*)d_in[0];
    const float* gt   = (const float*)d_in[1];
    const float* w1   = (const float*)d_in[2];
    const float* w2   = (const float*)d_in[3];
    float* out = (float*)d_out;

    int total = in_sizes[0];
    int N = total / (DIM * DIM * DIM);
    int nblk = N * NB * NB * NB;

    int smem_bytes = 2 * BLKV * (int)sizeof(float) + 512 * (int)sizeof(unsigned);
    cudaFuncSetAttribute(loss_main_kernel,
                         cudaFuncAttributeMaxDynamicSharedMemorySize, smem_bytes);

    loss_main_kernel<<<nblk, THREADS, smem_bytes>>>(pred, gt, w1, w2, out, nblk);
}

// round 14
// speedup vs baseline: 1.0417x; 1.0417x over previous
#include <cuda_runtime.h>
#include <math.h>

#define DIM 192
#define NB 12
#define BLKV 4096
#define THREADS 256
#define FULLM 0xffffffffu
#define NEG_INF (-3.402823466e+38f)
#define POS_INF (3.402823466e+38f)

// accumulators: [0]=sum(p*g) [1]=sum(p*p) [2]=sum(g*g) [3]=loss_cl
__device__ double g_acc[4] = {0.0, 0.0, 0.0, 0.0};
__device__ unsigned g_count = 0;

__device__ __forceinline__ float warp_sum(float v) {
#pragma unroll
    for (int o = 16; o; o >>= 1) v += __shfl_xor_sync(FULLM, v, o);
    return v;
}

// ---------------------------------------------------------------------------
// Thread (x,y) owns the 16-voxel z-column. lane = (x&1)*16 + y:
//   y+-1 : lane+-1 shfl     x^1 : lane^16 shfl (always a valid x neighbor)
//   other x : published smem column, 1 guarded LDS
// gt is binary: whole column = 16-bit mask (erode=AND cross, dilate=OR box,
// delta = e & ~d, skel |= delta) -- exact vs the f32 reference lattice.
//
// Register diet (occupancy 4): only cur[16] + skel[16] live in registers.
//  - erode is IN-PLACE (ascending k, one saved neighbor; shfls pass old value)
//  - dilate's "prev" level is read back from the buffer published last phase
//  - f32 exchange is TRIPLE-buffered so the phase-(k-1) buffer survives the
//    phase-k reads while phase k publishes elsewhere (>=1 barrier distance).
// ---------------------------------------------------------------------------

// in-place f32 erode: v <- min over z+-1, x (shfl + smem), y (shfl); +inf pad
__device__ __forceinline__ void erode_inplace(float (&v)[16],
                                              const float* __restrict__ fb,
                                              int to, bool xv, int y) {
    float below = POS_INF;
#pragma unroll
    for (int k = 0; k < 16; k++) {
        float old = v[k];
        float m = fminf(old, below);
        if (k < 15) m = fminf(m, v[k + 1]);
        m = fminf(m, __shfl_xor_sync(FULLM, old, 16));
        float o = fb[(k << 8) + to];
        if (xv) m = fminf(m, o);
        float yu = __shfl_up_sync(FULLM, old, 1);
        if (y > 0)  m = fminf(m, yu);
        float yd = __shfl_down_sync(FULLM, old, 1);
        if (y < 15) m = fminf(m, yd);
        v[k] = m;
        below = old;
    }
}

// f32 dilate (3x3x3 max, -inf pad) fused with skel init/update.
// e = current level (regs, also published in fb); prev level read from pb.
template <bool FIRST>
__device__ __forceinline__ void dilate_upd(const float (&e)[16], float (&skel)[16],
                                           const float* __restrict__ fb,
                                           const float* __restrict__ pb,
                                           int t, int to, bool xv, int y) {
    float xo0 = fb[to];
    float xo_m1 = NEG_INF;
#pragma unroll
    for (int k = 0; k < 16; k++) {
        float xo_p1 = (k < 15) ? fb[((k + 1) << 8) + to] : NEG_INF;
        // own z-max
        float mzk = e[k];
        if (k > 0)   mzk = fmaxf(mzk, e[k - 1]);
        if (k < 15)  mzk = fmaxf(mzk, e[k + 1]);
        // partner column z-max via one shfl of own z-max
        float m = fmaxf(mzk, __shfl_xor_sync(FULLM, mzk, 16));
        // other-x column z-max via rolling LDS window
        float zo = fmaxf(xo0, fmaxf(xo_m1, xo_p1));
        if (xv) m = fmaxf(m, zo);
        // y-pass on completed xz-max
        float yu = __shfl_up_sync(FULLM, m, 1);
        float yd = __shfl_down_sync(FULLM, m, 1);
        float d = m;
        if (y > 0)  d = fmaxf(d, yu);
        if (y < 15) d = fmaxf(d, yd);
        float prev = pb[(k << 8) + t];
        float delta = fmaxf(prev - d, 0.0f);
        if (FIRST) {
            skel[k] = delta;
        } else {
            float s = skel[k];
            skel[k] = s + fmaxf(delta - s * delta, 0.0f);
        }
        xo_m1 = xo0; xo0 = xo_p1;
    }
}

// bits erode (AND 7-cross, pads=1) reading published bits
__device__ __forceinline__ unsigned erode_bits(unsigned cur, const unsigned* __restrict__ ib,
                                               int to, bool xv, int y) {
    unsigned m = cur & ((cur << 1) | 1u) & ((cur >> 1) | 0x8000u);
    m &= __shfl_xor_sync(FULLM, cur, 16);
    unsigned ox = ib[to];
    if (xv) m &= ox;
    unsigned yu = __shfl_up_sync(FULLM, cur, 1);
    if (y > 0)  m &= yu;
    unsigned yd = __shfl_down_sync(FULLM, cur, 1);
    if (y < 15) m &= yd;
    return m & 0xFFFFu;
}

// bits dilate (OR 3x3x3 box, pads=0); other-x dz recomputed from published e-bits
__device__ __forceinline__ unsigned dilate_bits(unsigned e, const unsigned* __restrict__ ib,
                                                int to, bool xv, int y) {
    unsigned dz = e | (e << 1) | (e >> 1);
    unsigned dx = dz | __shfl_xor_sync(FULLM, dz, 16);
    unsigned ox = ib[to];
    if (xv) dx |= ox | (ox << 1) | (ox >> 1);
    unsigned d = dx;
    unsigned yu = __shfl_up_sync(FULLM, dx, 1);
    if (y > 0)  d |= yu;
    unsigned yd = __shfl_down_sync(FULLM, dx, 1);
    if (y < 15) d |= yd;
    return d & 0xFFFFu;
}

__device__ __forceinline__ double block_tversky(double tp, double fn, double fp) {
    const double s = 1e-8;
    double ab = fp + fn + s;
    double alpha = 0.5 + 0.5 * (fp + s) / ab;
    double beta  = 0.5 + 0.5 * (fn + s) / ab;
    return 1.0 - (tp + s) / (tp + alpha * fp + beta * fn + s);
}

extern __shared__ float smem[];

__global__ void __launch_bounds__(THREADS, 4)
loss_main_kernel(const float* __restrict__ pred, const float* __restrict__ gt,
                 const float* __restrict__ w1, const float* __restrict__ w2,
                 float* __restrict__ out, int nblk) {
    float* f0 = smem;                 // f32 exchange, phases 0,3
    float* f1 = smem + BLKV;          // f32 exchange, phases 1,4
    float* f2 = smem + 2 * BLKV;      // f32 exchange, phase 2
    unsigned* ib0 = (unsigned*)(smem + 3 * BLKV);   // bits exchange, even phases
    unsigned* ib1 = ib0 + 256;                      // bits exchange, odd phases
    __shared__ float red[8][6];
    __shared__ unsigned last_flag;

    int t = threadIdx.x;
    int b = blockIdx.x;
    int by = b % NB;
    int bx = (b / NB) % NB;
    int bz = (b / (NB * NB)) % NB;
    int n  = b / (NB * NB * NB);

    int base = n * DIM * DIM * DIM
             + (bz * 16) * DIM * DIM
             + (bx * 16) * DIM
             + (by * 16);

    int x = t >> 4;
    int y = t & 15;
    bool xv = (x & 1) ? (x < 15) : (x > 0);
    int to = xv ? ((x & 1) ? t + 16 : t - 16) : t;
    int lane = t & 31, w = t >> 5;

    // ---- load: pred->f32 col, gt->bitmask; dice partials banked early ----
    float cur[16];
    unsigned bA = 0;
    {
        float pg = 0.f, pp = 0.f;
#pragma unroll
        for (int k = 0; k < 16; k++) {
            int gi = base + k * DIM * DIM + x * DIM + y;
            float gv = gt[gi];
            float pv = pred[gi];
            cur[k] = pv;
            if (gv != 0.0f) { bA |= (1u << k); pg += pv; }
            pp += pv * pv;
        }
        float gg = (float)__popc(bA);
        float s0 = warp_sum(pg), s1 = warp_sum(pp), s2 = warp_sum(gg);
        if (lane == 0) { red[w][0] = s0; red[w][1] = s1; red[w][2] = s2; }
    }

    // NOTE: reference's boundary conv kernel is -(ones.at[13].set(26)) -- all
    // taps negative -- so (b > 0.1) is identically false, loss_bdr == 0. Dropped.

    float skel[16];
    unsigned bPrev, bskel = 0;

    // P0: publish e0; erode -> e1 (in place)
#pragma unroll
    for (int k = 0; k < 16; k++) f0[(k << 8) + t] = cur[k];
    ib0[t] = bA;
    __syncthreads();
    bPrev = bA; bA = erode_bits(bA, ib0, to, xv, y);
    erode_inplace(cur, f0, to, xv, y);

    // P1: publish e1; skel init (prev=e0 from f0); erode -> e2
#pragma unroll
    for (int k = 0; k < 16; k++) f1[(k << 8) + t] = cur[k];
    ib1[t] = bA;
    __syncthreads();
    dilate_upd<true>(cur, skel, f1, f0, t, to, xv, y);
    bskel |= bPrev & ~dilate_bits(bA, ib1, to, xv, y);
    bPrev = bA; bA = erode_bits(bA, ib1, to, xv, y);
    erode_inplace(cur, f1, to, xv, y);

    // P2: publish e2; update (prev=e1 from f1); erode -> e3
#pragma unroll
    for (int k = 0; k < 16; k++) f2[(k << 8) + t] = cur[k];
    ib0[t] = bA;
    __syncthreads();
    dilate_upd<false>(cur, skel, f2, f1, t, to, xv, y);
    bskel |= bPrev & ~dilate_bits(bA, ib0, to, xv, y);
    bPrev = bA; bA = erode_bits(bA, ib0, to, xv, y);
    erode_inplace(cur, f2, to, xv, y);

    // P3: publish e3; update (prev=e2 from f2); erode -> e4
#pragma unroll
    for (int k = 0; k < 16; k++) f0[(k << 8) + t] = cur[k];
    ib1[t] = bA;
    __syncthreads();
    dilate_upd<false>(cur, skel, f0, f2, t, to, xv, y);
    bskel |= bPrev & ~dilate_bits(bA, ib1, to, xv, y);
    bPrev = bA; bA = erode_bits(bA, ib1, to, xv, y);
    erode_inplace(cur, f0, to, xv, y);

    // P4: publish e4; final update (prev=e3 from f0) -- no erode
#pragma unroll
    for (int k = 0; k < 16; k++) f1[(k << 8) + t] = cur[k];
    ib0[t] = bA;
    __syncthreads();
    dilate_upd<false>(cur, skel, f1, f0, t, to, xv, y);
    bskel |= bPrev & ~dilate_bits(bA, ib0, to, xv, y);

    // ---- clDice tversky counts ----
    float tpc = 0.f, fnc = 0.f, fpc = 0.f;
#pragma unroll
    for (int k = 0; k < 16; k++) {
        float sp = skel[k];
        if ((bskel >> k) & 1u) {
            tpc += sp;
            fnc += 1.0f - sp;
        } else {
            fpc += sp;
        }
    }
    {
        float s3 = warp_sum(tpc), s4 = warp_sum(fnc), s5 = warp_sum(fpc);
        if (lane == 0) { red[w][3] = s3; red[w][4] = s4; red[w][5] = s5; }
    }
    __syncthreads();

    // ---- per-block accumulate + last-CTA finalize ----
    if (t == 0) {
        double s[6];
#pragma unroll
        for (int i = 0; i < 6; i++) {
            double acc = 0.0;
#pragma unroll
            for (int ww = 0; ww < 8; ww++) acc += (double)red[ww][i];
            s[i] = acc;
        }
        atomicAdd(&g_acc[0], s[0]);
        atomicAdd(&g_acc[1], s[1]);
        atomicAdd(&g_acc[2], s[2]);
        atomicAdd(&g_acc[3], block_tversky(s[3], s[4], s[5]));
        __threadfence();
        unsigned c = atomicAdd(&g_count, 1u);
        last_flag = (c == (unsigned)(nblk - 1)) ? 1u : 0u;
    }
    __syncthreads();

    if (last_flag && t == 0) {
        __threadfence();
        double pg = g_acc[0], pp = g_acc[1], gg = g_acc[2], cl = g_acc[3];
        double dice = 2.0 * pg / fmax(pp + gg, 1e-6);
        double dice_loss = 1.0 - dice;
        double w1s = (double)w1[0], w2s = (double)w2[0];
        double edge = (cl / (w2s * w2s)) / (2.0 * (double)nblk)
                    + log(1.0 + fabs(w1s) * fabs(w2s));
        out[0] = (float)((dice < 0.8) ? dice_loss : dice_loss + edge);
        g_acc[0] = 0.0; g_acc[1] = 0.0; g_acc[2] = 0.0; g_acc[3] = 0.0;
        g_count = 0u;
        __threadfence();
    }
}

extern "C" void kernel_launch(void* const* d_in, const int* in_sizes, int n_in,
                              void* d_out, int out_size) {
    const float* pred = (const float*)d_in[0];
    const float* gt   = (const float*)d_in[1];
    const float* w1   = (const float*)d_in[2];
    const float* w2   = (const float*)d_in[3];
    float* out = (float*)d_out;

    int total = in_sizes[0];
    int N = total / (DIM * DIM * DIM);
    int nblk = N * NB * NB * NB;

    int smem_bytes = 3 * BLKV * (int)sizeof(float) + 512 * (int)sizeof(unsigned);
    cudaFuncSetAttribute(loss_main_kernel,
                         cudaFuncAttributeMaxDynamicSharedMemorySize, smem_bytes);

    loss_main_kernel<<<nblk, THREADS, smem_bytes>>>(pred, gt, w1, w2, out, nblk);
}

// round 15
// speedup vs baseline: 1.1228x; 1.0778x over previous
#include <cuda_runtime.h>
#include <math.h>

#define DIM 192
#define NB 12
#define THREADS 256
#define FULLM 0xffffffffu
#define NEG_INF (-3.402823466e+38f)
#define POS_INF (3.402823466e+38f)

// exchange buffer: 2048 float2 per buffer; element (k,t) at pair j=k/2, comp k&1,
// float2 index j*256 + t  (64-bit accesses, conflict-free)
#define F2N 2048

// accumulators: [0]=sum(p*g) [1]=sum(p*p) [2]=sum(g*g) [3]=loss_cl
__device__ double g_acc[4] = {0.0, 0.0, 0.0, 0.0};
__device__ unsigned g_count = 0;

__device__ __forceinline__ float warp_sum(float v) {
#pragma unroll
    for (int o = 16; o; o >>= 1) v += __shfl_xor_sync(FULLM, v, o);
    return v;
}

// ---------------------------------------------------------------------------
// Thread (x,y) owns the 16-voxel z-column. lane = (x&1)*16 + y:
//   y+-1 : segmented shfl (width 16) -- out-of-segment clamps to self, which is
//          the identity for min/max => no guards needed (pads handled free)
//   x^1  : shfl_xor 16 (always a valid x neighbor)
//   other x : packed float2 smem column, LDS.64 (guarded by xv)
// gt is binary: whole column = 16-bit mask (erode=AND cross, dilate=OR box,
// delta = e & ~d, skel |= delta) -- exact vs the f32 reference lattice.
// Erode writes its output DIRECTLY to the next cyclic buffer (f0->f1->f2->f0),
// fusing the publish; WAR safety = one-barrier distance in the 3-buffer ring.
// ---------------------------------------------------------------------------

// in-place erode + store result to write-buffer. reads other-x from rb.
__device__ __forceinline__ void erode_store(float (&v)[16],
                                            const float2* __restrict__ rb,
                                            float2* __restrict__ wb,
                                            int t, int to, bool xv) {
    float below = POS_INF;
#pragma unroll
    for (int j = 0; j < 8; j++) {
        float2 ox = rb[j * 256 + to];
        float2 outp;
        {   // voxel k = 2j  (k+1 always valid since k <= 14)
            const int k = 2 * j;
            float old = v[k];
            float m = fminf(old, below);
            m = fminf(m, v[k + 1]);
            m = fminf(m, __shfl_xor_sync(FULLM, old, 16));
            if (xv) m = fminf(m, ox.x);
            m = fminf(m, __shfl_up_sync(FULLM, old, 1, 16));
            m = fminf(m, __shfl_down_sync(FULLM, old, 1, 16));
            below = old; v[k] = m; outp.x = m;
        }
        {   // voxel k = 2j+1
            const int k = 2 * j + 1;
            float old = v[k];
            float m = fminf(old, below);
            if (k < 15) m = fminf(m, v[k + 1]);
            m = fminf(m, __shfl_xor_sync(FULLM, old, 16));
            if (xv) m = fminf(m, ox.y);
            m = fminf(m, __shfl_up_sync(FULLM, old, 1, 16));
            m = fminf(m, __shfl_down_sync(FULLM, old, 1, 16));
            below = old; v[k] = m; outp.y = m;
        }
        wb[j * 256 + t] = outp;
    }
}

// dilate(e) (3x3x3 max, -inf pad) fused with skel init/update.
// e in regs (== level in eb); other-x z-window from eb; prev level from pb.
template <bool FIRST>
__device__ __forceinline__ void dilate_upd(const float (&e)[16], float (&skel)[16],
                                           const float2* __restrict__ eb,
                                           const float2* __restrict__ pb,
                                           int t, int to, bool xv) {
    float2 oxc = eb[to];
    float xo_m1 = NEG_INF;
#pragma unroll
    for (int j = 0; j < 8; j++) {
        float2 oxn = (j < 7) ? eb[(j + 1) * 256 + to] : make_float2(NEG_INF, NEG_INF);
        float2 pv = pb[j * 256 + t];
        {   // voxel k = 2j
            const int k = 2 * j;
            float mz = e[k];
            if (k > 0) mz = fmaxf(mz, e[k - 1]);
            mz = fmaxf(mz, e[k + 1]);
            float m = fmaxf(mz, __shfl_xor_sync(FULLM, mz, 16));
            float zo = fmaxf(fmaxf(xo_m1, oxc.x), oxc.y);
            if (xv) m = fmaxf(m, zo);
            float d = fmaxf(m, __shfl_up_sync(FULLM, m, 1, 16));
            d = fmaxf(d, __shfl_down_sync(FULLM, m, 1, 16));
            float delta = fmaxf(pv.x - d, 0.0f);
            if (FIRST) { skel[k] = delta; }
            else { float s = skel[k]; skel[k] = s + fmaxf(delta - s * delta, 0.0f); }
        }
        {   // voxel k = 2j+1
            const int k = 2 * j + 1;
            float mz = fmaxf(e[k], e[k - 1]);
            if (k < 15) mz = fmaxf(mz, e[k + 1]);
            float m = fmaxf(mz, __shfl_xor_sync(FULLM, mz, 16));
            float zo = fmaxf(fmaxf(oxc.x, oxc.y), oxn.x);
            if (xv) m = fmaxf(m, zo);
            float d = fmaxf(m, __shfl_up_sync(FULLM, m, 1, 16));
            d = fmaxf(d, __shfl_down_sync(FULLM, m, 1, 16));
            float delta = fmaxf(pv.y - d, 0.0f);
            if (FIRST) { skel[k] = delta; }
            else { float s = skel[k]; skel[k] = s + fmaxf(delta - s * delta, 0.0f); }
        }
        xo_m1 = oxc.y; oxc = oxn;
    }
}

// bits erode (AND 7-cross, pads=1)
__device__ __forceinline__ unsigned erode_bits(unsigned cur, const unsigned* __restrict__ ib,
                                               int to, bool xv) {
    unsigned m = cur & ((cur << 1) | 1u) & ((cur >> 1) | 0x8000u);
    m &= __shfl_xor_sync(FULLM, cur, 16);
    unsigned ox = ib[to];
    if (xv) m &= ox;
    unsigned yu = __shfl_up_sync(FULLM, cur, 1, 16);
    unsigned yd = __shfl_down_sync(FULLM, cur, 1, 16);
    // segmented clamp returns own value at pads; pad semantics for erode need
    // "all ones" there -- own value AND'd is NOT identity, so keep guards via
    // OR-in of self: m &= (boundary ? 0xFFFF : neighbor). Simplest: guards.
    return m & yu & yd & 0xFFFFu;   // see note below: boundary lanes get self, handled by caller guards
}

// bits dilate (OR 3x3x3 box, pads=0)
__device__ __forceinline__ unsigned dilate_bits(unsigned e, const unsigned* __restrict__ ib,
                                                int to, bool xv) {
    unsigned dz = e | (e << 1) | (e >> 1);
    unsigned dx = dz | __shfl_xor_sync(FULLM, dz, 16);
    unsigned ox = ib[to];
    if (xv) dx |= ox | (ox << 1) | (ox >> 1);
    unsigned d = dx | __shfl_up_sync(FULLM, dx, 1, 16) | __shfl_down_sync(FULLM, dx, 1, 16);
    return d & 0xFFFFu;
}

__device__ __forceinline__ double block_tversky(double tp, double fn, double fp) {
    const double s = 1e-8;
    double ab = fp + fn + s;
    double alpha = 0.5 + 0.5 * (fp + s) / ab;
    double beta  = 0.5 + 0.5 * (fn + s) / ab;
    return 1.0 - (tp + s) / (tp + alpha * fp + beta * fn + s);
}

extern __shared__ float2 smem2[];

__global__ void __launch_bounds__(THREADS, 4)
loss_main_kernel(const float* __restrict__ pred, const float* __restrict__ gt,
                 const float* __restrict__ w1, const float* __restrict__ w2,
                 float* __restrict__ out, int nblk) {
    float2* f0 = smem2;
    float2* f1 = smem2 + F2N;
    float2* f2 = smem2 + 2 * F2N;
    unsigned* ib0 = (unsigned*)(smem2 + 3 * F2N);
    unsigned* ib1 = ib0 + 256;
    __shared__ float red[8][6];
    __shared__ unsigned last_flag;

    int t = threadIdx.x;
    int b = blockIdx.x;
    int by = b % NB;
    int bx = (b / NB) % NB;
    int bz = (b / (NB * NB)) % NB;
    int n  = b / (NB * NB * NB);

    int base = n * DIM * DIM * DIM
             + (bz * 16) * DIM * DIM
             + (bx * 16) * DIM
             + (by * 16);

    int x = t >> 4;
    int y = t & 15;
    bool xv = (x & 1) ? (x < 15) : (x > 0);
    int to = xv ? ((x & 1) ? t + 16 : t - 16) : t;
    int lane = t & 31, w = t >> 5;

    // ---- load: pred->f32 col, gt->bitmask; dice partials banked early ----
    float cur[16];
    unsigned bA = 0;   // current bits level
    {
        float pg = 0.f, pp = 0.f;
#pragma unroll
        for (int k = 0; k < 16; k++) {
            int gi = base + k * DIM * DIM + x * DIM + y;
            float gv = gt[gi];
            float pv = pred[gi];
            cur[k] = pv;
            if (gv != 0.0f) { bA |= (1u << k); pg += pv; }
            pp += pv * pv;
        }
        float gg = (float)__popc(bA);
        float s0 = warp_sum(pg), s1 = warp_sum(pp), s2 = warp_sum(gg);
        if (lane == 0) { red[w][0] = s0; red[w][1] = s1; red[w][2] = s2; }
    }

    // NOTE: reference's boundary conv kernel is -(ones.at[13].set(26)) -- all
    // taps negative -- so (b > 0.1) is identically false, loss_bdr == 0. Dropped.
    // NOTE bits y-pads: gt erode needs pad=1 at y boundaries; segmented shfl
    // returns SELF there, and self AND'd with m is a subset of the correct
    // result ONLY if self >= pad... self & m <= m; correct would be m & 0xFFFF
    // (pad=all-ones = identity). Self-clamp = m & cur: WRONG unless cur bits
    // cover m bits. m is derived from cur by ANDs, so m <= cur bitwise
    // => m & cur == m. Self-clamp IS the identity here. Same for dilate:
    // d | self(dx) == d since dx is a term of d. Both safe.

    float skel[16];
    unsigned bPrev, bskel = 0;

    // P0: publish e0 (f32 packed -> f0, bits -> ib0); erode -> e1 (regs + f1)
#pragma unroll
    for (int j = 0; j < 8; j++)
        f0[j * 256 + t] = make_float2(cur[2 * j], cur[2 * j + 1]);
    ib0[t] = bA;
    __syncthreads();
    bPrev = bA; bA = erode_bits(bA, ib0, to, xv);
    erode_store(cur, f0, f1, t, to, xv);

    // P1: bits publish; dilate(e1;prev=e0) skel-init; erode -> e2 (f2)
    ib1[t] = bA;
    __syncthreads();
    dilate_upd<true>(cur, skel, f1, f0, t, to, xv);
    bskel |= bPrev & ~dilate_bits(bA, ib1, to, xv);
    bPrev = bA; bA = erode_bits(bA, ib1, to, xv);
    erode_store(cur, f1, f2, t, to, xv);

    // P2: dilate(e2;prev=e1); erode -> e3 (f0)
    ib0[t] = bA;
    __syncthreads();
    dilate_upd<false>(cur, skel, f2, f1, t, to, xv);
    bskel |= bPrev & ~dilate_bits(bA, ib0, to, xv);
    bPrev = bA; bA = erode_bits(bA, ib0, to, xv);
    erode_store(cur, f2, f0, t, to, xv);

    // P3: dilate(e3;prev=e2); erode -> e4 (f1)
    ib1[t] = bA;
    __syncthreads();
    dilate_upd<false>(cur, skel, f0, f2, t, to, xv);
    bskel |= bPrev & ~dilate_bits(bA, ib1, to, xv);
    bPrev = bA; bA = erode_bits(bA, ib1, to, xv);
    erode_store(cur, f0, f1, t, to, xv);

    // P4: dilate(e4;prev=e3) -- final update, no erode
    ib0[t] = bA;
    __syncthreads();
    dilate_upd<false>(cur, skel, f1, f0, t, to, xv);
    bskel |= bPrev & ~dilate_bits(bA, ib0, to, xv);

    // ---- clDice tversky counts ----
    float tpc = 0.f, fnc = 0.f, fpc = 0.f;
#pragma unroll
    for (int k = 0; k < 16; k++) {
        float sp = skel[k];
        if ((bskel >> k) & 1u) {
            tpc += sp;
            fnc += 1.0f - sp;
        } else {
            fpc += sp;
        }
    }
    {
        float s3 = warp_sum(tpc), s4 = warp_sum(fnc), s5 = warp_sum(fpc);
        if (lane == 0) { red[w][3] = s3; red[w][4] = s4; red[w][5] = s5; }
    }
    __syncthreads();

    // ---- per-block accumulate + last-CTA finalize ----
    if (t == 0) {
        double s[6];
#pragma unroll
        for (int i = 0; i < 6; i++) {
            double acc = 0.0;
#pragma unroll
            for (int ww = 0; ww < 8; ww++) acc += (double)red[ww][i];
            s[i] = acc;
        }
        atomicAdd(&g_acc[0], s[0]);
        atomicAdd(&g_acc[1], s[1]);
        atomicAdd(&g_acc[2], s[2]);
        atomicAdd(&g_acc[3], block_tversky(s[3], s[4], s[5]));
        __threadfence();
        unsigned c = atomicAdd(&g_count, 1u);
        last_flag = (c == (unsigned)(nblk - 1)) ? 1u : 0u;
    }
    __syncthreads();

    if (last_flag && t == 0) {
        __threadfence();
        double pg = g_acc[0], pp = g_acc[1], gg = g_acc[2], cl = g_acc[3];
        double dice = 2.0 * pg / fmax(pp + gg, 1e-6);
        double dice_loss = 1.0 - dice;
        double w1s = (double)w1[0], w2s = (double)w2[0];
        double edge = (cl / (w2s * w2s)) / (2.0 * (double)nblk)
                    + log(1.0 + fabs(w1s) * fabs(w2s));
        out[0] = (float)((dice < 0.8) ? dice_loss : dice_loss + edge);
        g_acc[0] = 0.0; g_acc[1] = 0.0; g_acc[2] = 0.0; g_acc[3] = 0.0;
        g_count = 0u;
        __threadfence();
    }
}

extern "C" void kernel_launch(void* const* d_in, const int* in_sizes, int n_in,
                              void* d_out, int out_size) {
    const float* pred = (const float*)d_in[0];
    const float* gt   = (const float*)d_in[1];
    const float* w1   = (const float*)d_in[2];
    const float* w2   = (const float*)d_in[3];
    float* out = (float*)d_out;

    int total = in_sizes[0];
    int N = total / (DIM * DIM * DIM);
    int nblk = N * NB * NB * NB;

    int smem_bytes = 3 * F2N * (int)sizeof(float2) + 512 * (int)sizeof(unsigned);
    cudaFuncSetAttribute(loss_main_kernel,
                         cudaFuncAttributeMaxDynamicSharedMemorySize, smem_bytes);

    loss_main_kernel<<<nblk, THREADS, smem_bytes>>>(pred, gt, w1, w2, out, nblk);
}

// round 16
// speedup vs baseline: 1.3634x; 1.2143x over previous
#include <cuda_runtime.h>
#include <math.h>

#define DIM 192
#define NB 12
#define THREADS 128
#define FULLM 0xffffffffu
#define NEG_INF (-3.402823466e+38f)
#define POS_INF (3.402823466e+38f)

// exchange buffer: levels stored as float2 z-pairs; element (col c, y, zpair j)
// at float2 index j*256 + c*16 + y.  Each buffer 2048 float2 = 16 KB.
#define F2N 2048

// accumulators: [0]=sum(p*g) [1]=sum(p*p) [2]=sum(g*g) [3]=loss_cl
__device__ double g_acc[4] = {0.0, 0.0, 0.0, 0.0};
__device__ unsigned g_count = 0;

__device__ __forceinline__ float warp_sum(float v) {
#pragma unroll
    for (int o = 16; o; o >>= 1) v += __shfl_xor_sync(FULLM, v, o);
    return v;
}

// ---------------------------------------------------------------------------
// Thread (xp, y) owns TWO x-adjacent 16-z columns: xA=2xp, xB=2xp+1.
//   x between the pair : REGISTERS (no exchange at all)
//   outer x (xA-1 / xB+1): published smem columns, guarded LDS.64
//   y+-1 : segmented shfl width 16 (self-clamp = identity for min/max/and/or
//          because the clamped operand already contains/bounds the result)
//   z    : registers
// gt is binary: two 16-bit masks per thread (erode=AND, dilate=OR, exact).
// Erode writes its output directly into the next ring buffer (f0->f1->f2->f0);
// dilate reads prev level from the ring. One barrier per publish, 5 total.
// ---------------------------------------------------------------------------

// in-place erode of both columns + store results to write-buffer
__device__ __forceinline__ void erode_store(float (&a)[16], float (&b)[16],
                                            const float2* __restrict__ rb,
                                            float2* __restrict__ wb,
                                            int t2a, int t2b, int tl, int tr,
                                            bool lv, bool rv) {
    float belowA = POS_INF, belowB = POS_INF;
#pragma unroll
    for (int j = 0; j < 8; j++) {
        float2 L = rb[j * 256 + tl];
        float2 R = rb[j * 256 + tr];
        float2 oA, oB;
        {   // k = 2j (k+1 always valid)
            const int k = 2 * j;
            float olda = a[k], oldb = b[k];
            float ma = fminf(fminf(olda, belowA), a[k + 1]);
            ma = fminf(ma, oldb);
            if (lv) ma = fminf(ma, L.x);
            ma = fminf(ma, __shfl_up_sync(FULLM, olda, 1, 16));
            ma = fminf(ma, __shfl_down_sync(FULLM, olda, 1, 16));
            float mb = fminf(fminf(oldb, belowB), b[k + 1]);
            mb = fminf(mb, olda);
            if (rv) mb = fminf(mb, R.x);
            mb = fminf(mb, __shfl_up_sync(FULLM, oldb, 1, 16));
            mb = fminf(mb, __shfl_down_sync(FULLM, oldb, 1, 16));
            belowA = olda; belowB = oldb;
            a[k] = ma; b[k] = mb; oA.x = ma; oB.x = mb;
        }
        {   // k = 2j+1
            const int k = 2 * j + 1;
            float olda = a[k], oldb = b[k];
            float ma = fminf(olda, belowA);
            if (k < 15) ma = fminf(ma, a[k + 1]);
            ma = fminf(ma, oldb);
            if (lv) ma = fminf(ma, L.y);
            ma = fminf(ma, __shfl_up_sync(FULLM, olda, 1, 16));
            ma = fminf(ma, __shfl_down_sync(FULLM, olda, 1, 16));
            float mb = fminf(oldb, belowB);
            if (k < 15) mb = fminf(mb, b[k + 1]);
            mb = fminf(mb, olda);
            if (rv) mb = fminf(mb, R.y);
            mb = fminf(mb, __shfl_up_sync(FULLM, oldb, 1, 16));
            mb = fminf(mb, __shfl_down_sync(FULLM, oldb, 1, 16));
            belowA = olda; belowB = oldb;
            a[k] = ma; b[k] = mb; oA.y = ma; oB.y = mb;
        }
        wb[j * 256 + t2a] = oA;
        wb[j * 256 + t2b] = oB;
    }
}

// dilate (3x3x3 max, -inf pad) of both columns fused with skel init/update.
// a,b = current level (regs, also in eb); prev level from pb.
template <bool FIRST>
__device__ __forceinline__ void dilate_upd(const float (&a)[16], const float (&b)[16],
                                           float (&sA)[16], float (&sB)[16],
                                           const float2* __restrict__ eb,
                                           const float2* __restrict__ pb,
                                           int t2a, int t2b, int tl, int tr,
                                           bool lv, bool rv) {
    float2 Lc = eb[tl], Rc = eb[tr];
    float L_m1 = NEG_INF, R_m1 = NEG_INF;
#pragma unroll
    for (int j = 0; j < 8; j++) {
        float2 Ln = (j < 7) ? eb[(j + 1) * 256 + tl] : make_float2(NEG_INF, NEG_INF);
        float2 Rn = (j < 7) ? eb[(j + 1) * 256 + tr] : make_float2(NEG_INF, NEG_INF);
        float2 pA = pb[j * 256 + t2a];
        float2 pB = pb[j * 256 + t2b];
        {   // k = 2j
            const int k = 2 * j;
            float za = a[k];
            if (k > 0) za = fmaxf(za, a[k - 1]);
            za = fmaxf(za, a[k + 1]);
            float zb = b[k];
            if (k > 0) zb = fmaxf(zb, b[k - 1]);
            zb = fmaxf(zb, b[k + 1]);
            float zl = fmaxf(fmaxf(L_m1, Lc.x), Lc.y);
            float zr = fmaxf(fmaxf(R_m1, Rc.x), Rc.y);
            float mA = fmaxf(za, zb); if (lv) mA = fmaxf(mA, zl);
            float mB = fmaxf(zb, za); if (rv) mB = fmaxf(mB, zr);
            float dA = fmaxf(mA, __shfl_up_sync(FULLM, mA, 1, 16));
            dA = fmaxf(dA, __shfl_down_sync(FULLM, mA, 1, 16));
            float dB = fmaxf(mB, __shfl_up_sync(FULLM, mB, 1, 16));
            dB = fmaxf(dB, __shfl_down_sync(FULLM, mB, 1, 16));
            float da = fmaxf(pA.x - dA, 0.0f);
            float db = fmaxf(pB.x - dB, 0.0f);
            if (FIRST) { sA[k] = da; sB[k] = db; }
            else {
                float s = sA[k]; sA[k] = s + fmaxf(da - s * da, 0.0f);
                s = sB[k];       sB[k] = s + fmaxf(db - s * db, 0.0f);
            }
        }
        {   // k = 2j+1
            const int k = 2 * j + 1;
            float za = fmaxf(a[k], a[k - 1]);
            if (k < 15) za = fmaxf(za, a[k + 1]);
            float zb = fmaxf(b[k], b[k - 1]);
            if (k < 15) zb = fmaxf(zb, b[k + 1]);
            float zl = fmaxf(fmaxf(Lc.x, Lc.y), Ln.x);
            float zr = fmaxf(fmaxf(Rc.x, Rc.y), Rn.x);
            float mA = fmaxf(za, zb); if (lv) mA = fmaxf(mA, zl);
            float mB = fmaxf(zb, za); if (rv) mB = fmaxf(mB, zr);
            float dA = fmaxf(mA, __shfl_up_sync(FULLM, mA, 1, 16));
            dA = fmaxf(dA, __shfl_down_sync(FULLM, mA, 1, 16));
            float dB = fmaxf(mB, __shfl_up_sync(FULLM, mB, 1, 16));
            dB = fmaxf(dB, __shfl_down_sync(FULLM, mB, 1, 16));
            float da = fmaxf(pA.y - dA, 0.0f);
            float db = fmaxf(pB.y - dB, 0.0f);
            if (FIRST) { sA[k] = da; sB[k] = db; }
            else {
                float s = sA[k]; sA[k] = s + fmaxf(da - s * da, 0.0f);
                s = sB[k];       sB[k] = s + fmaxf(db - s * db, 0.0f);
            }
        }
        L_m1 = Lc.y; Lc = Ln;
        R_m1 = Rc.y; Rc = Rn;
    }
}

// bits erode (AND 7-cross, pads=1), both columns. Self-clamped segmented shfl
// is identity: the result m is bitwise <= cur, so m & cur == m.
__device__ __forceinline__ void erode_bits2(unsigned& mA, unsigned& mB,
                                            const unsigned* __restrict__ ib,
                                            int tl, int tr, bool lv, bool rv) {
    unsigned cA = mA, cB = mB;
    unsigned eA = cA & ((cA << 1) | 1u) & ((cA >> 1) | 0x8000u) & cB;
    unsigned eB = cB & ((cB << 1) | 1u) & ((cB >> 1) | 0x8000u) & cA;
    unsigned L = ib[tl], R = ib[tr];
    if (lv) eA &= L;
    if (rv) eB &= R;
    eA &= __shfl_up_sync(FULLM, cA, 1, 16) & __shfl_down_sync(FULLM, cA, 1, 16);
    eB &= __shfl_up_sync(FULLM, cB, 1, 16) & __shfl_down_sync(FULLM, cB, 1, 16);
    mA = eA & 0xFFFFu; mB = eB & 0xFFFFu;
}

// bits dilate (OR box, pads=0), both columns; self-clamped shfl is identity
// since dx is a term of d.
__device__ __forceinline__ void dilate_bits2(unsigned eA, unsigned eB,
                                             unsigned& dA, unsigned& dB,
                                             const unsigned* __restrict__ ib,
                                             int tl, int tr, bool lv, bool rv) {
    unsigned zA = eA | (eA << 1) | (eA >> 1);
    unsigned zB = eB | (eB << 1) | (eB >> 1);
    unsigned L = ib[tl], R = ib[tr];
    unsigned xA = zA | zB;
    unsigned xB = zB | zA;
    if (lv) xA |= L | (L << 1) | (L >> 1);
    if (rv) xB |= R | (R << 1) | (R >> 1);
    dA = (xA | __shfl_up_sync(FULLM, xA, 1, 16) | __shfl_down_sync(FULLM, xA, 1, 16)) & 0xFFFFu;
    dB = (xB | __shfl_up_sync(FULLM, xB, 1, 16) | __shfl_down_sync(FULLM, xB, 1, 16)) & 0xFFFFu;
}

__device__ __forceinline__ double block_tversky(double tp, double fn, double fp) {
    const double s = 1e-8;
    double ab = fp + fn + s;
    double alpha = 0.5 + 0.5 * (fp + s) / ab;
    double beta  = 0.5 + 0.5 * (fn + s) / ab;
    return 1.0 - (tp + s) / (tp + alpha * fp + beta * fn + s);
}

extern __shared__ float2 smem2[];

__global__ void __launch_bounds__(THREADS, 4)
loss_main_kernel(const float* __restrict__ pred, const float* __restrict__ gt,
                 const float* __restrict__ w1, const float* __restrict__ w2,
                 float* __restrict__ out, int nblk) {
    float2* f0 = smem2;
    float2* f1 = smem2 + F2N;
    float2* f2 = smem2 + 2 * F2N;
    unsigned* ib0 = (unsigned*)(smem2 + 3 * F2N);   // 256 entries
    unsigned* ib1 = ib0 + 256;
    __shared__ float red[4][6];
    __shared__ unsigned last_flag;

    int t = threadIdx.x;
    int blk = blockIdx.x;
    int by = blk % NB;
    int bx = (blk / NB) % NB;
    int bz = (blk / (NB * NB)) % NB;
    int n  = blk / (NB * NB * NB);

    int base = n * DIM * DIM * DIM
             + (bz * 16) * DIM * DIM
             + (bx * 16) * DIM
             + (by * 16);

    int xp = t >> 4;           // x-pair 0..7
    int y  = t & 15;
    int t2a = (xp << 5) + y;   // col 2xp   index (c*16+y)
    int t2b = t2a + 16;        // col 2xp+1
    bool lv = xp > 0, rv = xp < 7;
    int tl = lv ? t2a - 16 : t2a;
    int tr = rv ? t2b + 16 : t2b;
    int lane = t & 31, w = t >> 5;

    // ---- load both columns; dice partials banked early ----
    float a[16], b[16];
    unsigned mA = 0, mB = 0;
    {
        float pg = 0.f, pp = 0.f;
        int giA = base + (2 * xp) * DIM + y;
#pragma unroll
        for (int k = 0; k < 16; k++) {
            float gva = gt[giA];
            float pva = pred[giA];
            float gvb = gt[giA + DIM];
            float pvb = pred[giA + DIM];
            a[k] = pva; b[k] = pvb;
            if (gva != 0.0f) { mA |= (1u << k); pg += pva; }
            if (gvb != 0.0f) { mB |= (1u << k); pg += pvb; }
            pp += pva * pva + pvb * pvb;
            giA += DIM * DIM;
        }
        float gg = (float)(__popc(mA) + __popc(mB));
        float s0 = warp_sum(pg), s1 = warp_sum(pp), s2 = warp_sum(gg);
        if (lane == 0) { red[w][0] = s0; red[w][1] = s1; red[w][2] = s2; }
    }

    // NOTE: reference's boundary conv kernel is -(ones.at[13].set(26)) -- all
    // taps negative -- so (b > 0.1) is identically false, loss_bdr == 0. Dropped.

    float sA[16], sB[16];
    unsigned pA_bits, pB_bits, skA = 0, skB = 0, dA, dB;

    // P0: publish e0 (f0 + ib0); bits erode; f32 erode -> e1 (regs + f1)
#pragma unroll
    for (int j = 0; j < 8; j++) {
        f0[j * 256 + t2a] = make_float2(a[2 * j], a[2 * j + 1]);
        f0[j * 256 + t2b] = make_float2(b[2 * j], b[2 * j + 1]);
    }
    ib0[t2a] = mA; ib0[t2b] = mB;
    __syncthreads();
    pA_bits = mA; pB_bits = mB;
    erode_bits2(mA, mB, ib0, tl, tr, lv, rv);
    erode_store(a, b, f0, f1, t2a, t2b, tl, tr, lv, rv);

    // P1: publish bits e1; dilate(e1; prev=e0) init; bits; erode -> e2 (f2)
    ib1[t2a] = mA; ib1[t2b] = mB;
    __syncthreads();
    dilate_upd<true>(a, b, sA, sB, f1, f0, t2a, t2b, tl, tr, lv, rv);
    dilate_bits2(mA, mB, dA, dB, ib1, tl, tr, lv, rv);
    skA |= pA_bits & ~dA; skB |= pB_bits & ~dB;
    pA_bits = mA; pB_bits = mB;
    erode_bits2(mA, mB, ib1, tl, tr, lv, rv);
    erode_store(a, b, f1, f2, t2a, t2b, tl, tr, lv, rv);

    // P2: dilate(e2; prev=e1); erode -> e3 (f0)
    ib0[t2a] = mA; ib0[t2b] = mB;
    __syncthreads();
    dilate_upd<false>(a, b, sA, sB, f2, f1, t2a, t2b, tl, tr, lv, rv);
    dilate_bits2(mA, mB, dA, dB, ib0, tl, tr, lv, rv);
    skA |= pA_bits & ~dA; skB |= pB_bits & ~dB;
    pA_bits = mA; pB_bits = mB;
    erode_bits2(mA, mB, ib0, tl, tr, lv, rv);
    erode_store(a, b, f2, f0, t2a, t2b, tl, tr, lv, rv);

    // P3: dilate(e3; prev=e2); erode -> e4 (f1)
    ib1[t2a] = mA; ib1[t2b] = mB;
    __syncthreads();
    dilate_upd<false>(a, b, sA, sB, f0, f2, t2a, t2b, tl, tr, lv, rv);
    dilate_bits2(mA, mB, dA, dB, ib1, tl, tr, lv, rv);
    skA |= pA_bits & ~dA; skB |= pB_bits & ~dB;
    pA_bits = mA; pB_bits = mB;
    erode_bits2(mA, mB, ib1, tl, tr, lv, rv);
    erode_store(a, b, f0, f1, t2a, t2b, tl, tr, lv, rv);

    // P4: dilate(e4; prev=e3) -- final update, no erode
    ib0[t2a] = mA; ib0[t2b] = mB;
    __syncthreads();
    dilate_upd<false>(a, b, sA, sB, f1, f0, t2a, t2b, tl, tr, lv, rv);
    dilate_bits2(mA, mB, dA, dB, ib0, tl, tr, lv, rv);
    skA |= pA_bits & ~dA; skB |= pB_bits & ~dB;

    // ---- clDice tversky counts ----
    float tpc = 0.f, fnc = 0.f, fpc = 0.f;
#pragma unroll
    for (int k = 0; k < 16; k++) {
        float spa = sA[k];
        if ((skA >> k) & 1u) { tpc += spa; fnc += 1.0f - spa; }
        else { fpc += spa; }
        float spb = sB[k];
        if ((skB >> k) & 1u) { tpc += spb; fnc += 1.0f - spb; }
        else { fpc += spb; }
    }
    {
        float s3 = warp_sum(tpc), s4 = warp_sum(fnc), s5 = warp_sum(fpc);
        if (lane == 0) { red[w][3] = s3; red[w][4] = s4; red[w][5] = s5; }
    }
    __syncthreads();

    // ---- per-block accumulate + last-CTA finalize ----
    if (t == 0) {
        double s[6];
#pragma unroll
        for (int i = 0; i < 6; i++) {
            double acc = 0.0;
#pragma unroll
            for (int ww = 0; ww < 4; ww++) acc += (double)red[ww][i];
            s[i] = acc;
        }
        atomicAdd(&g_acc[0], s[0]);
        atomicAdd(&g_acc[1], s[1]);
        atomicAdd(&g_acc[2], s[2]);
        atomicAdd(&g_acc[3], block_tversky(s[3], s[4], s[5]));
        __threadfence();
        unsigned c = atomicAdd(&g_count, 1u);
        last_flag = (c == (unsigned)(nblk - 1)) ? 1u : 0u;
    }
    __syncthreads();

    if (last_flag && t == 0) {
        __threadfence();
        double pg = g_acc[0], pp = g_acc[1], gg = g_acc[2], cl = g_acc[3];
        double dice = 2.0 * pg / fmax(pp + gg, 1e-6);
        double dice_loss = 1.0 - dice;
        double w1s = (double)w1[0], w2s = (double)w2[0];
        double edge = (cl / (w2s * w2s)) / (2.0 * (double)nblk)
                    + log(1.0 + fabs(w1s) * fabs(w2s));
        out[0] = (float)((dice < 0.8) ? dice_loss : dice_loss + edge);
        g_acc[0] = 0.0; g_acc[1] = 0.0; g_acc[2] = 0.0; g_acc[3] = 0.0;
        g_count = 0u;
        __threadfence();
    }
}

extern "C" void kernel_launch(void* const* d_in, const int* in_sizes, int n_in,
                              void* d_out, int out_size) {
    const float* pred = (const float*)d_in[0];
    const float* gt   = (const float*)d_in[1];
    const float* w1   = (const float*)d_in[2];
    const float* w2   = (const float*)d_in[3];
    float* out = (float*)d_out;

    int total = in_sizes[0];
    int N = total / (DIM * DIM * DIM);
    int nblk = N * NB * NB * NB;

    int smem_bytes = 3 * F2N * (int)sizeof(float2) + 512 * (int)sizeof(unsigned);
    cudaFuncSetAttribute(loss_main_kernel,
                         cudaFuncAttributeMaxDynamicSharedMemorySize, smem_bytes);

    loss_main_kernel<<<nblk, THREADS, smem_bytes>>>(pred, gt, w1, w2, out, nblk);
}